// round 1
// baseline (speedup 1.0000x reference)
#include <cuda_runtime.h>

#define T_LEN 2048
#define B_LEN 2048
#define HID   32
#define DF    8
#define DP    8
#define DS    24
#define WARPS_PER_CTA 7
#define NTHREADS (WARPS_PER_CTA * 32)
#define NCTAS 147   // ceil(1024 warps / 7)

__device__ __forceinline__ float tanh_fast(float x) {
    float y;
    asm("tanh.approx.f32 %0, %1;" : "=f"(y) : "f"(x));
    return y;
}

struct WarpSmem {
    float2 hf[HID];
    float2 hp[HID];
    float2 hs0[HID];
    float2 hs1[HID];
    float2 hs2[HID];
    float2 xf[DF];
    float2 xp[DP];
    float2 xs[DS];
};

__global__ void __launch_bounds__(NTHREADS, 1)
chive_kernel(const float* __restrict__ frnn, const float* __restrict__ phrnn,
             const float* __restrict__ syl,
             const float* __restrict__ Wxf, const float* __restrict__ Whf,
             const float* __restrict__ bf,
             const float* __restrict__ Wxp, const float* __restrict__ Whp,
             const float* __restrict__ bp,
             const float* __restrict__ Wxs, const float* __restrict__ Whs,
             const float* __restrict__ bs,
             const int* __restrict__ fclock, const int* __restrict__ pclock,
             const int* __restrict__ sfreq,
             float* __restrict__ out)
{
    __shared__ unsigned char flags_sm[T_LEN];
    __shared__ WarpSmem wsm[WARPS_PER_CTA];

    const int tid = threadIdx.x;
    // Precompute warp-uniform update flags for all timesteps (per CTA, 2KB smem).
    for (int t = tid; t < T_LEN; t += NTHREADS) {
        int fl = ((t % (fclock[t] + 1)) == 0) ? 1 : 0;
        if ((t % (pclock[t] + 1)) == 0) fl |= 2;
        if (sfreq[t] == 1) fl |= 4;
        flags_sm[t] = (unsigned char)fl;
    }
    __syncthreads();

    const int warp = tid >> 5;
    const int lane = tid & 31;
    const int wgid = blockIdx.x * WARPS_PER_CTA + warp;
    const int b0 = wgid * 2;
    if (b0 >= B_LEN) return;   // after the only __syncthreads
    const int b1 = b0 + 1;

    WarpSmem& S = wsm[warp];
    S.hf[lane]  = make_float2(0.f, 0.f);
    S.hp[lane]  = make_float2(0.f, 0.f);
    S.hs0[lane] = make_float2(0.f, 0.f);
    S.hs1[lane] = make_float2(0.f, 0.f);
    S.hs2[lane] = make_float2(0.f, 0.f);

    // Per-lane weight columns in registers (lane j holds column j).
    float wxf[DF], whf[HID], wxp[DP], whp[HID], wxs[HID], whs[HID];
    #pragma unroll
    for (int i = 0; i < DF; i++)  wxf[i] = Wxf[i * HID + lane];
    #pragma unroll
    for (int i = 0; i < HID; i++) whf[i] = Whf[i * HID + lane];
    #pragma unroll
    for (int i = 0; i < DP; i++)  wxp[i] = Wxp[i * HID + lane];
    #pragma unroll
    for (int i = 0; i < HID; i++) whp[i] = Whp[i * HID + lane];
    #pragma unroll
    for (int i = 0; i < HID; i++) wxs[i] = Wxs[i * HID + lane];
    #pragma unroll
    for (int i = 0; i < HID; i++) whs[i] = Whs[i * HID + lane];
    const float rbf = bf[lane], rbp = bp[lane], rbs = bs[lane];

    // Prefetched inputs for the current step (loaded one iteration ahead).
    float f0 = 0.f, f1 = 0.f, p0 = 0.f, p1 = 0.f, s0 = 0.f, s1 = 0.f;
    {
        const int fl0 = flags_sm[0];
        if ((fl0 & 1) && lane < DF) {
            f0 = frnn[(size_t)b0 * DF + lane];
            f1 = frnn[(size_t)b1 * DF + lane];
        }
        if ((fl0 & 2) && lane < DP) {
            p0 = phrnn[(size_t)b0 * DP + lane];
            p1 = phrnn[(size_t)b1 * DP + lane];
        }
        if ((fl0 & 4) && lane < DS) {
            s0 = syl[(size_t)b0 * DS + lane];
            s1 = syl[(size_t)b1 * DS + lane];
        }
    }
    __syncwarp();

    for (int t = 0; t < T_LEN; t++) {
        const int fl = flags_sm[t];

        // Prefetch inputs for t+1 (gated by its flags) to hide DRAM latency.
        float nf0 = 0.f, nf1 = 0.f, np0 = 0.f, np1 = 0.f, ns0 = 0.f, ns1 = 0.f;
        if (t + 1 < T_LEN) {
            const int nfl = flags_sm[t + 1];
            const size_t base = (size_t)(t + 1) * B_LEN;
            if ((nfl & 1) && lane < DF) {
                nf0 = frnn[(base + b0) * DF + lane];
                nf1 = frnn[(base + b1) * DF + lane];
            }
            if ((nfl & 2) && lane < DP) {
                np0 = phrnn[(base + b0) * DP + lane];
                np1 = phrnn[(base + b1) * DP + lane];
            }
            if ((nfl & 4) && lane < DS) {
                ns0 = syl[(base + b0) * DS + lane];
                ns1 = syl[(base + b1) * DS + lane];
            }
        }

        if (fl) {
            // Stage this step's inputs as interleaved (b0,b1) pairs.
            if ((fl & 1) && lane < DF) S.xf[lane] = make_float2(f0, f1);
            if ((fl & 2) && lane < DP) S.xp[lane] = make_float2(p0, p1);
            if ((fl & 4) && lane < DS) S.xs[lane] = make_float2(s0, s1);
            __syncwarp();

            float hf0 = 0.f, hf1 = 0.f, hp0 = 0.f, hp1 = 0.f;
            const bool wf = (fl & 1) != 0, wp = (fl & 2) != 0;

            if (wf) {
                float a0 = rbf, a1 = rbf, c0 = 0.f, c1 = 0.f;
                #pragma unroll
                for (int i = 0; i < DF; i++) {
                    float2 xx = S.xf[i];
                    a0 += xx.x * wxf[i]; a1 += xx.y * wxf[i];
                }
                #pragma unroll
                for (int k = 0; k < HID; k++) {
                    float2 hh = S.hf[k];
                    c0 += hh.x * whf[k]; c1 += hh.y * whf[k];
                }
                hf0 = tanh_fast(a0 + c0); hf1 = tanh_fast(a1 + c1);
            }
            if (wp) {
                float a0 = rbp, a1 = rbp, c0 = 0.f, c1 = 0.f;
                #pragma unroll
                for (int i = 0; i < DP; i++) {
                    float2 xx = S.xp[i];
                    a0 += xx.x * wxp[i]; a1 += xx.y * wxp[i];
                }
                #pragma unroll
                for (int k = 0; k < HID; k++) {
                    float2 hh = S.hp[k];
                    c0 += hh.x * whp[k]; c1 += hh.y * whp[k];
                }
                hp0 = tanh_fast(a0 + c0); hp1 = tanh_fast(a1 + c1);
            }
            if (wf || wp) {
                __syncwarp();   // all lanes finished reading old hf/hp
                if (wf) S.hf[lane] = make_float2(hf0, hf1);
                if (wp) S.hp[lane] = make_float2(hp0, hp1);
                __syncwarp();   // new hf/hp visible to s-cell reads
            }

            if (fl & 4) {
                float a00 = rbs, a01 = rbs, a10 = rbs, a11 = rbs, a20 = rbs, a21 = rbs;
                float c00 = 0.f, c01 = 0.f, c10 = 0.f, c11 = 0.f, c20 = 0.f, c21 = 0.f;
                #pragma unroll
                for (int k = 0; k < HID; k++) {
                    const float wx = wxs[k], wh = whs[k];
                    float2 xa = S.hf[k];  a00 += xa.x * wx; a01 += xa.y * wx;
                    float2 ha = S.hs0[k]; c00 += ha.x * wh; c01 += ha.y * wh;
                    float2 xb = S.hp[k];  a10 += xb.x * wx; a11 += xb.y * wx;
                    float2 hb = S.hs1[k]; c10 += hb.x * wh; c11 += hb.y * wh;
                    float2 hc = S.hs2[k]; c20 += hc.x * wh; c21 += hc.y * wh;
                }
                #pragma unroll
                for (int k = 0; k < DS; k++) {   // padded input: cols 24..31 are zero
                    float2 xx = S.xs[k];
                    a20 += xx.x * wxs[k]; a21 += xx.y * wxs[k];
                }
                const float o00 = tanh_fast(a00 + c00), o01 = tanh_fast(a01 + c01);
                const float o10 = tanh_fast(a10 + c10), o11 = tanh_fast(a11 + c11);
                const float o20 = tanh_fast(a20 + c20), o21 = tanh_fast(a21 + c21);
                __syncwarp();   // all lanes finished reading old hs
                S.hs0[lane] = make_float2(o00, o01);
                S.hs1[lane] = make_float2(o10, o11);
                S.hs2[lane] = make_float2(o20, o21);
            }
        }

        f0 = nf0; f1 = nf1; p0 = np0; p1 = np1; s0 = ns0; s1 = ns1;
    }

    // Emit final h_s [3, B, H]; lane j wrote its own slot, same-thread read is safe.
    const float2 r0 = S.hs0[lane];
    const float2 r1 = S.hs1[lane];
    const float2 r2 = S.hs2[lane];
    out[((size_t)0 * B_LEN + b0) * HID + lane] = r0.x;
    out[((size_t)0 * B_LEN + b1) * HID + lane] = r0.y;
    out[((size_t)1 * B_LEN + b0) * HID + lane] = r1.x;
    out[((size_t)1 * B_LEN + b1) * HID + lane] = r1.y;
    out[((size_t)2 * B_LEN + b0) * HID + lane] = r2.x;
    out[((size_t)2 * B_LEN + b1) * HID + lane] = r2.y;
}

extern "C" void kernel_launch(void* const* d_in, const int* in_sizes, int n_in,
                              void* d_out, int out_size) {
    (void)in_sizes; (void)n_in; (void)out_size;
    chive_kernel<<<NCTAS, NTHREADS>>>(
        (const float*)d_in[0],  (const float*)d_in[1],  (const float*)d_in[2],
        (const float*)d_in[3],  (const float*)d_in[4],  (const float*)d_in[5],
        (const float*)d_in[6],  (const float*)d_in[7],  (const float*)d_in[8],
        (const float*)d_in[9],  (const float*)d_in[10], (const float*)d_in[11],
        (const int*)d_in[12],   (const int*)d_in[13],   (const int*)d_in[14],
        (float*)d_out);
}